// round 10
// baseline (speedup 1.0000x reference)
#include <cuda_runtime.h>
#include <cuda_fp16.h>
#include <cstdint>

#define TOKENS 8192
#define IN_F   4096
#define OUT_F  4096
#define BM 128
#define BN 256
#define BK 128
#define NK_ITERS (IN_F / BK)    // 32
#define LDSR (BK + 8)           // 136 halves = 272B pitch (272 % 128 = 16 -> conflict-free ldmatrix)
#define STAGES 2
#define A_STAGE_ELEMS (BM * LDSR)   // 17408
#define B_STAGE_ELEMS (BN * LDSR)   // 34816
#define SMEM_BYTES (STAGES * (A_STAGE_ELEMS + B_STAGE_ELEMS) * 2)   // 208896 (204 KB)

// ---------------- scratch (device globals: allowed; no allocs) -------------
__device__ __align__(16) __half g_Xh[(size_t)TOKENS * IN_F];   // 64 MB fp16 activations
__device__ __align__(16) __half g_Wh[(size_t)OUT_F * IN_F];    // 32 MB fp16 dequant weights

__device__ __forceinline__ uint32_t smem_u32(const void* p) {
    return (uint32_t)__cvta_generic_to_shared(p);
}

__device__ __forceinline__ void ldm_x4(uint32_t& r0, uint32_t& r1,
                                       uint32_t& r2, uint32_t& r3, uint32_t addr) {
    asm volatile("ldmatrix.sync.aligned.m8n8.x4.shared.b16 {%0,%1,%2,%3}, [%4];"
                 : "=r"(r0), "=r"(r1), "=r"(r2), "=r"(r3) : "r"(addr));
}

__device__ __forceinline__ void mma16816(float* c, const uint32_t* a,
                                         uint32_t b0, uint32_t b1) {
    asm volatile(
        "mma.sync.aligned.m16n8k16.row.col.f32.f16.f16.f32 "
        "{%0,%1,%2,%3}, {%4,%5,%6,%7}, {%8,%9}, {%0,%1,%2,%3};"
        : "+f"(c[0]), "+f"(c[1]), "+f"(c[2]), "+f"(c[3])
        : "r"(a[0]), "r"(a[1]), "r"(a[2]), "r"(a[3]), "r"(b0), "r"(b1));
}

// ---------------- prep kernels ---------------------------------------------
__global__ void convert_x_kernel(const float* __restrict__ x) {
    size_t i = (size_t)blockIdx.x * blockDim.x + threadIdx.x;  // one float4
    if (i >= (size_t)TOKENS * IN_F / 4) return;
    float4 v = reinterpret_cast<const float4*>(x)[i];
    __half2* out = reinterpret_cast<__half2*>(g_Xh);
    out[2 * i]     = __floats2half2_rn(v.x, v.y);
    out[2 * i + 1] = __floats2half2_rn(v.z, v.w);
}

__global__ void dequant_w_kernel(const int* __restrict__ wp,
                                 const float* __restrict__ ws) {
    size_t i = (size_t)blockIdx.x * blockDim.x + threadIdx.x;  // one packed byte
    if (i >= (size_t)OUT_F * (IN_F / 2)) return;
    int n = (int)(i >> 11);          // / 2048
    int j = (int)(i & 2047);
    int p = wp[i];
    float s = ws[n * (IN_F / 128) + (j >> 6)];   // group = (2j)/128 = j/64
    float lo = (float)((p & 15) - 8) * s;        // even column 2j
    float hi = (float)(((p >> 4) & 15) - 8) * s; // odd  column 2j+1
    reinterpret_cast<__half2*>(g_Wh)[i] = __floats2half2_rn(lo, hi);
}

// ---------------- HMMA GEMM -------------------------------------------------
// C[M,N] = Xh[M,K] @ Wh[N,K]^T. CTA tile 128x256, 8 warps (2x4), warp tile
// 64x64, BK=128, 2-stage cp.async double-buffer -> only 32 barriers total.
// Refill split into eighths interleaved across the 8 kk-steps (3 cp.async
// per thread per step). Single-buffered fragments (round-8 proven).
__global__ void __launch_bounds__(256, 1)
gemm_hmma_kernel(float* __restrict__ C) {
    extern __shared__ __align__(16) __half smem[];
    __half* sA = smem;                                 // STAGES x BM x LDSR
    __half* sB = smem + STAGES * A_STAGE_ELEMS;        // STAGES x BN x LDSR

    const int tid = threadIdx.x;
    const int wid = tid >> 5;
    const int lid = tid & 31;
    const int quad = lid >> 3;
    const int l8 = lid & 7;
    const int m0 = blockIdx.y * BM;
    const int n0 = blockIdx.x * BN;
    const int m_off = (wid & 1) * 64;      // 2 warp rows
    const int n_off = (wid >> 1) * 64;     // 4 warp cols

    const __half* baseA = g_Xh + (size_t)m0 * IN_F;
    const __half* baseB = g_Wh + (size_t)n0 * IN_F;

    float acc[4][8][4];
#pragma unroll
    for (int mi = 0; mi < 4; mi++)
#pragma unroll
        for (int nf = 0; nf < 8; nf++)
#pragma unroll
            for (int r = 0; r < 4; r++) acc[mi][nf][r] = 0.0f;

    // Stage loader eighth e (0..7): A chunk tid+256e (1/thr of 2048),
    // B chunks tid+256*(2e), tid+256*(2e+1) (2/thr of 4096).
    // 16 chunks of 16B per row (BK=128). Lanes 0..15 cover one 256B row pair.
    auto load_eighth = [&](int st, int kc, int e) {
        const __half* pa = baseA + kc * BK;
        const __half* pb = baseB + kc * BK;
        __half* da = sA + st * A_STAGE_ELEMS;
        __half* db = sB + st * B_STAGE_ELEMS;
        {
            int chunk = tid + 256 * e;
            int row = chunk >> 4, ch = chunk & 15;
            uint32_t dst = smem_u32(da + row * LDSR + ch * 8);
            asm volatile("cp.async.cg.shared.global [%0], [%1], 16;"
                         :: "r"(dst), "l"((const void*)(pa + (size_t)row * IN_F + ch * 8)));
        }
#pragma unroll
        for (int i = 0; i < 2; i++) {
            int chunk = tid + 256 * (2 * e + i);
            int row = chunk >> 4, ch = chunk & 15;
            uint32_t dst = smem_u32(db + row * LDSR + ch * 8);
            asm volatile("cp.async.cg.shared.global [%0], [%1], 16;"
                         :: "r"(dst), "l"((const void*)(pb + (size_t)row * IN_F + ch * 8)));
        }
    };

#pragma unroll
    for (int e = 0; e < 8; e++) load_eighth(0, 0, e);
    asm volatile("cp.async.commit_group;");

    for (int kc = 0; kc < NK_ITERS; kc++) {
        asm volatile("cp.async.wait_group 0;");   // stage cur complete
        __syncthreads();                          // all warps done with other stage

        const int cur = kc & 1;
        const __half* cA = sA + cur * A_STAGE_ELEMS;
        const __half* cB = sB + cur * B_STAGE_ELEMS;
        const bool refill = (kc + 1 < NK_ITERS);
        const int next_st = cur ^ 1;

#pragma unroll
        for (int kk = 0; kk < 8; kk++) {
            const int k0 = kk * 16;
            uint32_t a[4][4];
#pragma unroll
            for (int mi = 0; mi < 4; mi++) {
                uint32_t addr = smem_u32(
                    cA + (m_off + mi * 16 + (quad & 1) * 8 + l8) * LDSR
                       + k0 + (quad >> 1) * 8);
                ldm_x4(a[mi][0], a[mi][1], a[mi][2], a[mi][3], addr);
            }
            uint32_t b[4][4];
#pragma unroll
            for (int nb = 0; nb < 4; nb++) {
                uint32_t addr = smem_u32(
                    cB + (n_off + nb * 16 + (quad >> 1) * 8 + l8) * LDSR
                       + k0 + (quad & 1) * 8);
                ldm_x4(b[nb][0], b[nb][1], b[nb][2], b[nb][3], addr);
            }
#pragma unroll
            for (int mi = 0; mi < 4; mi++)
#pragma unroll
                for (int nf = 0; nf < 8; nf++) {
                    const uint32_t* bf = &b[nf >> 1][(nf & 1) * 2];
                    mma16816(acc[mi][nf], a[mi], bf[0], bf[1]);
                }

            // Interleaved refill: one eighth per kk-step, commit on the last.
            if (refill) load_eighth(next_st, kc + 1, kk);
            if (kk == 7) asm volatile("cp.async.commit_group;");
        }
    }

    // Epilogue: c0,c1 at (row = t/4, col = 2*(t%4)); c2,c3 at row+8.
    const int er = lid >> 2;
    const int ec = (lid & 3) * 2;
#pragma unroll
    for (int mi = 0; mi < 4; mi++) {
        float* r0 = C + (size_t)(m0 + m_off + mi * 16 + er) * OUT_F + n0 + n_off;
        float* r1 = r0 + (size_t)8 * OUT_F;
#pragma unroll
        for (int nf = 0; nf < 8; nf++) {
            float2 v0 = make_float2(acc[mi][nf][0], acc[mi][nf][1]);
            float2 v1 = make_float2(acc[mi][nf][2], acc[mi][nf][3]);
            *reinterpret_cast<float2*>(r0 + nf * 8 + ec) = v0;
            *reinterpret_cast<float2*>(r1 + nf * 8 + ec) = v1;
        }
    }
}

// ---------------- launch -----------------------------------------------------
extern "C" void kernel_launch(void* const* d_in, const int* in_sizes, int n_in,
                              void* d_out, int out_size) {
    const float* x  = (const float*)d_in[0];
    const int*   wp = (const int*)d_in[1];
    const float* ws = (const float*)d_in[2];
    float* out = (float*)d_out;

    cudaFuncSetAttribute(gemm_hmma_kernel,
                         cudaFuncAttributeMaxDynamicSharedMemorySize, SMEM_BYTES);

    {
        size_t n4 = (size_t)TOKENS * IN_F / 4;
        convert_x_kernel<<<(unsigned)((n4 + 255) / 256), 256>>>(x);
    }
    {
        size_t np = (size_t)OUT_F * (IN_F / 2);
        dequant_w_kernel<<<(unsigned)((np + 255) / 256), 256>>>(wp, ws);
    }
    {
        dim3 grid(OUT_F / BN, TOKENS / BM);   // 16 x 64 = 1024 CTAs
        gemm_hmma_kernel<<<grid, 256, SMEM_BYTES>>>(out);
    }
}

// round 12
// speedup vs baseline: 1.1488x; 1.1488x over previous
#include <cuda_runtime.h>
#include <cuda_fp16.h>
#include <cstdint>

#define TOKENS 8192
#define IN_F   4096
#define OUT_F  4096
#define BM 128
#define BN 256
#define BK 128
#define NK_ITERS (IN_F / BK)    // 32
#define LDSR (BK + 8)           // 136 halves = 272B pitch (272 % 128 = 16 -> conflict-free ldmatrix)
#define STAGES 2
#define A_STAGE_ELEMS (BM * LDSR)   // 17408
#define B_STAGE_ELEMS (BN * LDSR)   // 34816
#define SMEM_BYTES (STAGES * (A_STAGE_ELEMS + B_STAGE_ELEMS) * 2)   // 208896 (204 KB)

// ---------------- scratch (device globals: allowed; no allocs) -------------
__device__ __align__(16) __half g_Xh[(size_t)TOKENS * IN_F];   // 64 MB fp16 activations
__device__ __align__(16) __half g_Wh[(size_t)OUT_F * IN_F];    // 32 MB fp16 dequant weights

__device__ __forceinline__ uint32_t smem_u32(const void* p) {
    return (uint32_t)__cvta_generic_to_shared(p);
}

__device__ __forceinline__ void ldm_x4(uint32_t& r0, uint32_t& r1,
                                       uint32_t& r2, uint32_t& r3, uint32_t addr) {
    asm volatile("ldmatrix.sync.aligned.m8n8.x4.shared.b16 {%0,%1,%2,%3}, [%4];"
                 : "=r"(r0), "=r"(r1), "=r"(r2), "=r"(r3) : "r"(addr));
}

__device__ __forceinline__ void mma16816(float* c, const uint32_t* a,
                                         uint32_t b0, uint32_t b1) {
    asm volatile(
        "mma.sync.aligned.m16n8k16.row.col.f32.f16.f16.f32 "
        "{%0,%1,%2,%3}, {%4,%5,%6,%7}, {%8,%9}, {%0,%1,%2,%3};"
        : "+f"(c[0]), "+f"(c[1]), "+f"(c[2]), "+f"(c[3])
        : "r"(a[0]), "r"(a[1]), "r"(a[2]), "r"(a[3]), "r"(b0), "r"(b1));
}

// ---------------- prep kernels ---------------------------------------------
__global__ void convert_x_kernel(const float* __restrict__ x) {
    size_t i = (size_t)blockIdx.x * blockDim.x + threadIdx.x;  // one float4
    if (i >= (size_t)TOKENS * IN_F / 4) return;
    float4 v = reinterpret_cast<const float4*>(x)[i];
    __half2* out = reinterpret_cast<__half2*>(g_Xh);
    out[2 * i]     = __floats2half2_rn(v.x, v.y);
    out[2 * i + 1] = __floats2half2_rn(v.z, v.w);
}

__global__ void dequant_w_kernel(const int* __restrict__ wp,
                                 const float* __restrict__ ws) {
    size_t i = (size_t)blockIdx.x * blockDim.x + threadIdx.x;  // one packed byte
    if (i >= (size_t)OUT_F * (IN_F / 2)) return;
    int n = (int)(i >> 11);          // / 2048
    int j = (int)(i & 2047);
    int p = wp[i];
    float s = ws[n * (IN_F / 128) + (j >> 6)];   // group = (2j)/128 = j/64
    float lo = (float)((p & 15) - 8) * s;        // even column 2j
    float hi = (float)(((p >> 4) & 15) - 8) * s; // odd  column 2j+1
    reinterpret_cast<__half2*>(g_Wh)[i] = __floats2half2_rn(lo, hi);
}

// ---------------- HMMA GEMM -------------------------------------------------
// C[M,N] = Xh[M,K] @ Wh[N,K]^T. CTA tile 128x256, 8 warps (2x4), warp tile
// 64x64, BK=128, 2-stage double-buffer (32 barriers). Refill FRONT-LOADED:
// two eighths after each of kk=0..3's MMA blocks, commit at kk=3, leaving
// kk=4..7 (~1200 cyc) of slack before the next iteration's wait_group 0.
__global__ void __launch_bounds__(256, 1)
gemm_hmma_kernel(float* __restrict__ C) {
    extern __shared__ __align__(16) __half smem[];
    __half* sA = smem;                                 // STAGES x BM x LDSR
    __half* sB = smem + STAGES * A_STAGE_ELEMS;        // STAGES x BN x LDSR

    const int tid = threadIdx.x;
    const int wid = tid >> 5;
    const int lid = tid & 31;
    const int quad = lid >> 3;
    const int l8 = lid & 7;
    const int m0 = blockIdx.y * BM;
    const int n0 = blockIdx.x * BN;
    const int m_off = (wid & 1) * 64;      // 2 warp rows
    const int n_off = (wid >> 1) * 64;     // 4 warp cols

    const __half* baseA = g_Xh + (size_t)m0 * IN_F;
    const __half* baseB = g_Wh + (size_t)n0 * IN_F;

    float acc[4][8][4];
#pragma unroll
    for (int mi = 0; mi < 4; mi++)
#pragma unroll
        for (int nf = 0; nf < 8; nf++)
#pragma unroll
            for (int r = 0; r < 4; r++) acc[mi][nf][r] = 0.0f;

    // Stage loader eighth e (0..7): A chunk tid+256e (1/thr of 2048),
    // B chunks tid+256*(2e), tid+256*(2e+1) (2/thr of 4096).
    auto load_eighth = [&](int st, int kc, int e) {
        const __half* pa = baseA + kc * BK;
        const __half* pb = baseB + kc * BK;
        __half* da = sA + st * A_STAGE_ELEMS;
        __half* db = sB + st * B_STAGE_ELEMS;
        {
            int chunk = tid + 256 * e;
            int row = chunk >> 4, ch = chunk & 15;
            uint32_t dst = smem_u32(da + row * LDSR + ch * 8);
            asm volatile("cp.async.cg.shared.global [%0], [%1], 16;"
                         :: "r"(dst), "l"((const void*)(pa + (size_t)row * IN_F + ch * 8)));
        }
#pragma unroll
        for (int i = 0; i < 2; i++) {
            int chunk = tid + 256 * (2 * e + i);
            int row = chunk >> 4, ch = chunk & 15;
            uint32_t dst = smem_u32(db + row * LDSR + ch * 8);
            asm volatile("cp.async.cg.shared.global [%0], [%1], 16;"
                         :: "r"(dst), "l"((const void*)(pb + (size_t)row * IN_F + ch * 8)));
        }
    };

#pragma unroll
    for (int e = 0; e < 8; e++) load_eighth(0, 0, e);
    asm volatile("cp.async.commit_group;");

    for (int kc = 0; kc < NK_ITERS; kc++) {
        asm volatile("cp.async.wait_group 0;");   // stage cur complete
        __syncthreads();                          // all warps done with other stage

        const int cur = kc & 1;
        const __half* cA = sA + cur * A_STAGE_ELEMS;
        const __half* cB = sB + cur * B_STAGE_ELEMS;
        const bool refill = (kc + 1 < NK_ITERS);
        const int next_st = cur ^ 1;

#pragma unroll
        for (int kk = 0; kk < 8; kk++) {
            const int k0 = kk * 16;
            uint32_t a[4][4];
#pragma unroll
            for (int mi = 0; mi < 4; mi++) {
                uint32_t addr = smem_u32(
                    cA + (m_off + mi * 16 + (quad & 1) * 8 + l8) * LDSR
                       + k0 + (quad >> 1) * 8);
                ldm_x4(a[mi][0], a[mi][1], a[mi][2], a[mi][3], addr);
            }
            uint32_t b[4][4];
#pragma unroll
            for (int nb = 0; nb < 4; nb++) {
                uint32_t addr = smem_u32(
                    cB + (n_off + nb * 16 + (quad >> 1) * 8 + l8) * LDSR
                       + k0 + (quad & 1) * 8);
                ldm_x4(b[nb][0], b[nb][1], b[nb][2], b[nb][3], addr);
            }
#pragma unroll
            for (int mi = 0; mi < 4; mi++)
#pragma unroll
                for (int nf = 0; nf < 8; nf++) {
                    const uint32_t* bf = &b[nf >> 1][(nf & 1) * 2];
                    mma16816(acc[mi][nf], a[mi], bf[0], bf[1]);
                }

            // Front-loaded refill: two eighths per kk-step for kk=0..3,
            // commit at kk=3 -> kk=4..7 of slack before the next wait.
            if (refill && kk < 4) {
                load_eighth(next_st, kc + 1, 2 * kk);
                load_eighth(next_st, kc + 1, 2 * kk + 1);
            }
            if (kk == 3) asm volatile("cp.async.commit_group;");
        }
    }

    // Epilogue: c0,c1 at (row = t/4, col = 2*(t%4)); c2,c3 at row+8.
    const int er = lid >> 2;
    const int ec = (lid & 3) * 2;
#pragma unroll
    for (int mi = 0; mi < 4; mi++) {
        float* r0 = C + (size_t)(m0 + m_off + mi * 16 + er) * OUT_F + n0 + n_off;
        float* r1 = r0 + (size_t)8 * OUT_F;
#pragma unroll
        for (int nf = 0; nf < 8; nf++) {
            float2 v0 = make_float2(acc[mi][nf][0], acc[mi][nf][1]);
            float2 v1 = make_float2(acc[mi][nf][2], acc[mi][nf][3]);
            *reinterpret_cast<float2*>(r0 + nf * 8 + ec) = v0;
            *reinterpret_cast<float2*>(r1 + nf * 8 + ec) = v1;
        }
    }
}

// ---------------- launch -----------------------------------------------------
extern "C" void kernel_launch(void* const* d_in, const int* in_sizes, int n_in,
                              void* d_out, int out_size) {
    const float* x  = (const float*)d_in[0];
    const int*   wp = (const int*)d_in[1];
    const float* ws = (const float*)d_in[2];
    float* out = (float*)d_out;

    cudaFuncSetAttribute(gemm_hmma_kernel,
                         cudaFuncAttributeMaxDynamicSharedMemorySize, SMEM_BYTES);

    {
        size_t n4 = (size_t)TOKENS * IN_F / 4;
        convert_x_kernel<<<(unsigned)((n4 + 255) / 256), 256>>>(x);
    }
    {
        size_t np = (size_t)OUT_F * (IN_F / 2);
        dequant_w_kernel<<<(unsigned)((np + 255) / 256), 256>>>(wp, ws);
    }
    {
        dim3 grid(OUT_F / BN, TOKENS / BM);   // 16 x 64 = 1024 CTAs
        gemm_hmma_kernel<<<grid, 256, SMEM_BYTES>>>(out);
    }
}